// round 11
// baseline (speedup 1.0000x reference)
#include <cuda_runtime.h>
#include <cuda_fp16.h>
#include <math.h>
#include <stdint.h>

// Problem: B=4, S=4096, D=2048, E=64, K=2
#define M_TOKENS 16384
#define D_DIM    2048
#define E_EXP    64
#define TM       112                   // tokens per CTA (7 m16 blocks)
#define NWARPS   7
#define NTHREADS (NWARPS * 32)         // 224
#define NCTA     147                   // 146 full + 1 partial (32 tokens)
#define NCH      64                    // k32 chunks
#define WSCALE   1024.0f               // exact pow2 pre-scale of W

// Stage: xs [112 tok x 36 f32] + wh [2 kstep x 8 pair x 64 e] + wl
#define XS_BYTES (TM * 36 * 4)         // 16128
#define WH_OFF   XS_BYTES
#define WH_BYTES 4096
#define WL_OFF   (WH_OFF + WH_BYTES)
#define STAGE_BYTES (WL_OFF + WH_BYTES)    // 24320
#define NSTAGE 3
#define DYN_BYTES (NSTAGE * STAGE_BYTES)   // 72960

__device__ float g_partials[NCTA * 128];
__device__ unsigned int g_done = 0;
// W split images, scaled by WSCALE: u32 f16x2 of k-pair, layout [kstep][pair][e]
__device__ __align__(16) uint32_t g_wh[(D_DIM / 2) * E_EXP];
__device__ __align__(16) uint32_t g_wl[(D_DIM / 2) * E_EXP];

#define CP16(smem_a, gptr) \
    asm volatile("cp.async.cg.shared.global [%0], [%1], 16;" \
                 :: "r"(smem_a), "l"(gptr) : "memory")
#define CP_COMMIT() asm volatile("cp.async.commit_group;" ::: "memory")
#define CP_WAIT1()  asm volatile("cp.async.wait_group 1;" ::: "memory")

static __device__ __forceinline__ uint32_t smem_u32(const void* p) {
    uint32_t r;
    asm("{ .reg .u64 t; cvta.to.shared.u64 t, %1; cvt.u32.u64 %0, t; }"
        : "=r"(r) : "l"(p));
    return r;
}
static __device__ __forceinline__ void mma_f16(float* d,
        uint32_t a0, uint32_t a1, uint32_t a2, uint32_t a3,
        uint32_t b0, uint32_t b1) {
    asm volatile(
        "mma.sync.aligned.m16n8k16.row.col.f32.f16.f16.f32 "
        "{%0,%1,%2,%3},{%4,%5,%6,%7},{%8,%9},{%0,%1,%2,%3};"
        : "+f"(d[0]), "+f"(d[1]), "+f"(d[2]), "+f"(d[3])
        : "r"(a0), "r"(a1), "r"(a2), "r"(a3), "r"(b0), "r"(b1));
}
// split float2 (k-pair) into hi f16x2 and lo f16x2 (lo = v - hi, exact in f32)
static __device__ __forceinline__ void split_pair(float2 v, uint32_t& h, uint32_t& l) {
    __half2 hh = __floats2half2_rn(v.x, v.y);
    float2 hb = __half22float2(hh);
    __half2 ll = __floats2half2_rn(v.x - hb.x, v.y - hb.y);
    h = *reinterpret_cast<uint32_t*>(&hh);
    l = *reinterpret_cast<uint32_t*>(&ll);
}

// pre-kernel: coalesced row-major reads; build scaled hi/lo images [kstep][pair][e]
__global__ void wsplit_kernel(const float* __restrict__ W)
{
    int g = blockIdx.x * blockDim.x + threadIdx.x;   // 0..16383
    int e  = g >> 8;                                 // 0..63
    int k8 = g & 255;                                // 8 k-values each
    const float4* wp = reinterpret_cast<const float4*>(
        W + (size_t)e * D_DIM + k8 * 8);
    float4 v0 = wp[0], v1 = wp[1];
    float vv[8] = {v0.x, v0.y, v0.z, v0.w, v1.x, v1.y, v1.z, v1.w};
#pragma unroll
    for (int i = 0; i < 4; i++) {
        int kp = k8 * 4 + i;
        float2 v = make_float2(vv[2 * i] * WSCALE, vv[2 * i + 1] * WSCALE);
        uint32_t h, l;
        split_pair(v, h, l);
        int idx = ((kp >> 3) * 8 + (kp & 7)) * 64 + e;
        g_wh[idx] = h;
        g_wl[idx] = l;
    }
}

__global__ __launch_bounds__(NTHREADS, 1)
void router_f16(const float* __restrict__ x, float* __restrict__ out)
{
    extern __shared__ __align__(16) char dsm[];
    __shared__ int tops[TM][2];
    __shared__ unsigned int s_last;

    const int tid  = threadIdx.x;
    const int wid  = tid >> 5;     // warp owns m-block wid (tokens 16w..16w+15)
    const int lane = tid & 31;
    const int qr   = lane >> 2, qc = lane & 3;
    const int cta  = blockIdx.x;
    const size_t tbase = (size_t)cta * TM;
    const int valid = (int)((M_TOKENS - tbase) < TM ? (M_TOKENS - tbase) : TM);
    const uint32_t sb0 = smem_u32(dsm);

    // ---- async loader: chunk c -> stage s (x rows clamped for partial CTA) ----
    auto load_chunk = [&](int c, int s) {
        const int k0 = c * 32;
        const uint32_t bs = sb0 + (uint32_t)s * STAGE_BYTES;
#pragma unroll
        for (int p = 0; p < 4; p++) {                 // xs: 896 segs of 16B
            int seg = tid + p * NTHREADS;
            int t = seg >> 3, sk = seg & 7;
            size_t grow = tbase + t;
            if (grow > M_TOKENS - 1) grow = M_TOKENS - 1;
            const float* g = x + grow * (size_t)D_DIM + k0 + sk * 4;
            CP16(bs + (uint32_t)(t * 36 + sk * 4) * 4, g);
        }
#pragma unroll
        for (int p = 0; p < 2; p++) {                 // wh: 256 segs
            int seg = tid + p * NTHREADS;
            if (seg < 256) {
                const uint32_t* g = g_wh + (size_t)c * 1024 + seg * 4;
                CP16(bs + WH_OFF + (uint32_t)seg * 16, g);
            }
        }
#pragma unroll
        for (int p = 0; p < 2; p++) {                 // wl: 256 segs
            int seg = tid + p * NTHREADS;
            if (seg < 256) {
                const uint32_t* g = g_wl + (size_t)c * 1024 + seg * 4;
                CP16(bs + WL_OFF + (uint32_t)seg * 16, g);
            }
        }
    };

    float acc[8][4], sum32[8][4];
#pragma unroll
    for (int n = 0; n < 8; n++)
#pragma unroll
        for (int j = 0; j < 4; j++) { acc[n][j] = 0.0f; sum32[n][j] = 0.0f; }

    load_chunk(0, 0); CP_COMMIT();
    load_chunk(1, 1); CP_COMMIT();

    const int ar0 = (wid * 16 + qr) * 36;
    const int ar1 = ar0 + 8 * 36;

#pragma unroll 1
    for (int c = 0; c < NCH; c++) {
        CP_WAIT1();                    // group c complete (c+1 may pend)
        __syncthreads();               // data visible; all warps done chunk c-1
        if (c + 2 < NCH) load_chunk(c + 2, (c + 2) % NSTAGE);
        CP_COMMIT();                   // uniform group count

        const int s = c % NSTAGE;
        const float* xs = reinterpret_cast<const float*>(dsm + s * STAGE_BYTES);
        const uint32_t whb = sb0 + (uint32_t)s * STAGE_BYTES + WH_OFF;
        const uint32_t wlb = whb + WH_BYTES;

#pragma unroll
        for (int ks = 0; ks < 2; ks++) {
            const int kb = ks * 16 + 2 * qc;
            uint32_t a0h, a0l, a1h, a1l, a2h, a2l, a3h, a3l;
            split_pair(*reinterpret_cast<const float2*>(&xs[ar0 + kb]),     a0h, a0l);
            split_pair(*reinterpret_cast<const float2*>(&xs[ar1 + kb]),     a1h, a1l);
            split_pair(*reinterpret_cast<const float2*>(&xs[ar0 + kb + 8]), a2h, a2l);
            split_pair(*reinterpret_cast<const float2*>(&xs[ar1 + kb + 8]), a3h, a3l);

#pragma unroll
            for (int n = 0; n < 8; n++) {
                const uint32_t off0 = (uint32_t)(((ks * 8 + qc) * 64) + n * 8 + qr) * 4;
                const uint32_t off1 = (uint32_t)(((ks * 8 + qc + 4) * 64) + n * 8 + qr) * 4;
                uint32_t bh0, bh1, bl0, bl1;
                asm volatile("ld.shared.b32 %0, [%1];" : "=r"(bh0) : "r"(whb + off0));
                asm volatile("ld.shared.b32 %0, [%1];" : "=r"(bh1) : "r"(whb + off1));
                asm volatile("ld.shared.b32 %0, [%1];" : "=r"(bl0) : "r"(wlb + off0));
                asm volatile("ld.shared.b32 %0, [%1];" : "=r"(bl1) : "r"(wlb + off1));
                mma_f16(acc[n], a0h, a1h, a2h, a3h, bh0, bh1);
                mma_f16(acc[n], a0h, a1h, a2h, a3h, bl0, bl1);
                mma_f16(acc[n], a0l, a1l, a2l, a3l, bh0, bh1);
            }
        }

        if ((c & 15) == 15) {          // drain: caps fp32 accumulate chain at 96
#pragma unroll
            for (int n = 0; n < 8; n++)
#pragma unroll
                for (int j = 0; j < 4; j++) {
                    sum32[n][j] += acc[n][j];
                    acc[n][j] = 0.0f;
                }
        }
    }
    __syncthreads();

    // ---- epilogue: logits (unscaled) into overlay [112][66] ----
    float* probs = reinterpret_cast<float*>(dsm);
    const float inv_ws = 1.0f / WSCALE;
    {
        const int tr0 = wid * 16 + qr;
#pragma unroll
        for (int n = 0; n < 8; n++) {
            const int cb = n * 8 + qc * 2;
            *reinterpret_cast<float2*>(&probs[tr0 * 66 + cb]) =
                make_float2(sum32[n][0] * inv_ws, sum32[n][1] * inv_ws);
            *reinterpret_cast<float2*>(&probs[(tr0 + 8) * 66 + cb]) =
                make_float2(sum32[n][2] * inv_ws, sum32[n][3] * inv_ws);
        }
    }
    __syncthreads();

    // per-token: softmax + top-2 + gates + outputs (invalid rows zeroed)
    if (tid < TM) {
        const int t = tid;
        if (t < valid) {
            float f[64];
#pragma unroll
            for (int e = 0; e < E_EXP; e++) f[e] = probs[t * 66 + e];
            float mx = f[0];
#pragma unroll
            for (int e = 1; e < E_EXP; e++) mx = fmaxf(mx, f[e]);
            float S = 0.0f, b1 = -1.0f, b2 = -1.0f;
            int i1 = 0, i2 = 0;
#pragma unroll
            for (int e = 0; e < E_EXP; e++) {
                float v = expf(f[e] - mx);
                f[e] = v;
                S += v;
                if (v > b1) { b2 = b1; i2 = i1; b1 = v; i1 = e; }
                else if (v > b2) { b2 = v; i2 = e; }
            }
            const float invS = 1.0f / S;
#pragma unroll
            for (int e = 0; e < E_EXP; e++) probs[t * 66 + e] = f[e] * invS;
            tops[t][0] = i1;
            tops[t][1] = i2;

            const float p1 = b1 * invS, p2 = b2 * invS;
            const float denom = p1 + p2 + 1e-9f;
            const size_t gt = tbase + t;
            out[gt * 2 + 0] = (float)i1;
            out[gt * 2 + 1] = (float)i2;
            out[(size_t)M_TOKENS * 2 + gt * 2 + 0] = p1 / denom;
            out[(size_t)M_TOKENS * 2 + gt * 2 + 1] = p2 / denom;
        } else {
#pragma unroll
            for (int e = 0; e < E_EXP; e++) probs[t * 66 + e] = 0.0f;
            tops[t][0] = -1;
            tops[t][1] = -1;
        }
    }
    __syncthreads();

    // deterministic per-CTA partials
    if (tid < E_EXP) {
        const int e = tid;
        float cnt = 0.0f, sp = 0.0f;
#pragma unroll 4
        for (int t = 0; t < TM; t++) {
            sp  += probs[t * 66 + e];
            cnt += (float)((tops[t][0] == e) + (tops[t][1] == e));
        }
        g_partials[cta * 128 + e]      = cnt;
        g_partials[cta * 128 + 64 + e] = sp;
    }
    __syncthreads();

    // ---- fused aux: last CTA to finish reduces (values order-fixed) ----
    if (tid == 0) {
        __threadfence();
        s_last = atomicAdd(&g_done, 1u);
    }
    __syncthreads();
    if (s_last == NCTA - 1) {
        __threadfence();
        float* sC = probs;            // reuse overlay
        float* sP = probs + 64;
        float* red = probs + 128;
        if (tid < 128) {
            const int e = tid & 63, h = tid >> 6;
            float sv = 0.0f;
#pragma unroll 4
            for (int b = 0; b < NCTA; b++)
                sv += __ldcg(&g_partials[b * 128 + h * 64 + e]);
            if (h == 0) sC[e] = sv; else sP[e] = sv;
        }
        __syncthreads();
        if (tid < 64) red[tid] = sC[tid] * sP[tid];
        __syncthreads();
#pragma unroll
        for (int s = 32; s > 0; s >>= 1) {
            if (tid < s) red[tid] += red[tid + s];
            __syncthreads();
        }
        if (tid == 0) {
            out[(size_t)M_TOKENS * 4] =
                0.01f * 64.0f * red[0] / (32768.0f * 16384.0f);
            g_done = 0;               // reset for next graph replay
        }
    }
}

extern "C" void kernel_launch(void* const* d_in, const int* in_sizes, int n_in,
                              void* d_out, int out_size)
{
    const float* x = (const float*)d_in[0];   // [4,4096,2048] f32
    const float* W = (const float*)d_in[1];   // [64,2048] f32
    float* out = (float*)d_out;               // [32768 idx | 32768 gates | 1 aux]

    cudaFuncSetAttribute(router_f16,
                         cudaFuncAttributeMaxDynamicSharedMemorySize, DYN_BYTES);

    wsplit_kernel<<<64, 256>>>(W);
    router_f16<<<NCTA, NTHREADS, DYN_BYTES>>>(x, out);
}

// round 12
// speedup vs baseline: 1.4140x; 1.4140x over previous
#include <cuda_runtime.h>
#include <cuda_fp16.h>
#include <math.h>
#include <stdint.h>

// Problem: B=4, S=4096, D=2048, E=64, K=2
#define M_TOKENS 16384
#define D_DIM    2048
#define E_EXP    64
#define TM       128                   // tokens per CTA (8 m16 blocks)
#define NTHREADS 256
#define NCTA     (M_TOKENS / TM)       // 128 (exact, no partial CTA)
#define NCH      64                    // k32 chunks
#define WSCALE   1024.0f               // exact pow2 pre-scale of W

// Stage: xs [128 tok x 40 f32] + wh [2 ks x 8 pair x 72 words] + wl (same)
// xs stride 40 words: LDS.64 bank = (8qr+2qc) mod 32 -> conflict-free
// B pair stride 72 words: bank = (8qc+8n+qr) mod 32 -> conflict-free
#define XS_WSTRIDE 40
#define XS_BYTES  (TM * XS_WSTRIDE * 4)     // 20480
#define B_PSTRIDE 288                        // 72 words * 4B (16B-aligned)
#define WH_OFF    XS_BYTES
#define WH_BYTES  (2 * 8 * B_PSTRIDE)        // 4608
#define WL_OFF    (WH_OFF + WH_BYTES)
#define STAGE_BYTES (WL_OFF + WH_BYTES)      // 29696
#define NSTAGE 3
#define DYN_BYTES (NSTAGE * STAGE_BYTES)     // 89088

__device__ float g_partials[NCTA * 128];
__device__ unsigned int g_done = 0;
// W split images (packed in gmem): u32 f16x2 per k-pair, layout [kstep][pair][e]
__device__ __align__(16) uint32_t g_wh[(D_DIM / 2) * E_EXP];
__device__ __align__(16) uint32_t g_wl[(D_DIM / 2) * E_EXP];

#define CP16(smem_a, gptr) \
    asm volatile("cp.async.cg.shared.global [%0], [%1], 16;" \
                 :: "r"(smem_a), "l"(gptr) : "memory")
#define CP_COMMIT() asm volatile("cp.async.commit_group;" ::: "memory")
#define CP_WAIT1()  asm volatile("cp.async.wait_group 1;" ::: "memory")

static __device__ __forceinline__ uint32_t smem_u32(const void* p) {
    uint32_t r;
    asm("{ .reg .u64 t; cvta.to.shared.u64 t, %1; cvt.u32.u64 %0, t; }"
        : "=r"(r) : "l"(p));
    return r;
}
static __device__ __forceinline__ void mma_f16(float* d,
        uint32_t a0, uint32_t a1, uint32_t a2, uint32_t a3,
        uint32_t b0, uint32_t b1) {
    asm volatile(
        "mma.sync.aligned.m16n8k16.row.col.f32.f16.f16.f32 "
        "{%0,%1,%2,%3},{%4,%5,%6,%7},{%8,%9},{%0,%1,%2,%3};"
        : "+f"(d[0]), "+f"(d[1]), "+f"(d[2]), "+f"(d[3])
        : "r"(a0), "r"(a1), "r"(a2), "r"(a3), "r"(b0), "r"(b1));
}
// split float2 (k-pair) into hi f16x2 and lo f16x2 (lo = v - hi, exact in f32)
static __device__ __forceinline__ void split_pair(float2 v, uint32_t& h, uint32_t& l) {
    __half2 hh = __floats2half2_rn(v.x, v.y);
    float2 hb = __half22float2(hh);
    __half2 ll = __floats2half2_rn(v.x - hb.x, v.y - hb.y);
    h = *reinterpret_cast<uint32_t*>(&hh);
    l = *reinterpret_cast<uint32_t*>(&ll);
}

// pre-kernel: coalesced row-major reads; scaled hi/lo images [kstep][pair][e]
__global__ void wsplit_kernel(const float* __restrict__ W)
{
    int g = blockIdx.x * blockDim.x + threadIdx.x;   // 0..16383
    int e  = g >> 8;                                 // 0..63
    int k8 = g & 255;                                // covers 8 k-values
    const float4* wp = reinterpret_cast<const float4*>(
        W + (size_t)e * D_DIM + k8 * 8);
    float4 v0 = wp[0], v1 = wp[1];
    float vv[8] = {v0.x, v0.y, v0.z, v0.w, v1.x, v1.y, v1.z, v1.w};
#pragma unroll
    for (int i = 0; i < 4; i++) {
        int kp = k8 * 4 + i;
        float2 v = make_float2(vv[2 * i] * WSCALE, vv[2 * i + 1] * WSCALE);
        uint32_t h, l;
        split_pair(v, h, l);
        int idx = ((kp >> 3) * 8 + (kp & 7)) * 64 + e;
        g_wh[idx] = h;
        g_wl[idx] = l;
    }
}

__global__ __launch_bounds__(NTHREADS, 1)
void router_f16(const float* __restrict__ x, float* __restrict__ out)
{
    extern __shared__ __align__(16) char dsm[];
    __shared__ int tops[TM][2];
    __shared__ unsigned int s_last;

    const int tid  = threadIdx.x;
    const int wid  = tid >> 5;     // warp owns m-block wid (tokens 16w..16w+15)
    const int lane = tid & 31;
    const int qr   = lane >> 2, qc = lane & 3;
    const int cta  = blockIdx.x;
    const size_t tbase = (size_t)cta * TM;
    const uint32_t sb0 = smem_u32(dsm);

    // ---- async loader: chunk c -> stage s ----
    auto load_chunk = [&](int c, int s) {
        const int k0 = c * 32;
        const uint32_t bs = sb0 + (uint32_t)s * STAGE_BYTES;
#pragma unroll
        for (int p = 0; p < 4; p++) {                 // xs: 1024 segs of 16B
            int seg = tid + p * NTHREADS;
            int t = seg >> 3, sk = seg & 7;
            const float* g = x + (tbase + t) * (size_t)D_DIM + k0 + sk * 4;
            CP16(bs + (uint32_t)(t * (XS_WSTRIDE * 4) + sk * 16), g);
        }
        {   // wh: 512 packed segs -> padded [ks*8+pair][72w] rows
            int seg = tid;                            // 0..255 (2 per thread)
#pragma unroll
            for (int p = 0; p < 2; p++) {
                int sg = seg + p * NTHREADS;          // 0..511
                int pr = sg >> 4, s16 = sg & 15;      // pair-row 0..31? (2ks*8=16 rows, 16 segs each -> 256)
                // NOTE: 4096B packed = 256 segs; do same for wl below
                if (sg < 256) {
                    const uint32_t* g = g_wh + (size_t)c * 1024 + sg * 4;
                    CP16(bs + WH_OFF + (uint32_t)(pr * B_PSTRIDE + s16 * 16), g);
                } else {
                    int sg2 = sg - 256;
                    int pr2 = sg2 >> 4, s162 = sg2 & 15;
                    const uint32_t* g = g_wl + (size_t)c * 1024 + sg2 * 4;
                    CP16(bs + WL_OFF + (uint32_t)(pr2 * B_PSTRIDE + s162 * 16), g);
                }
            }
        }
    };

    float acc[8][4], sum32[8][4];
#pragma unroll
    for (int n = 0; n < 8; n++)
#pragma unroll
        for (int j = 0; j < 4; j++) { acc[n][j] = 0.0f; sum32[n][j] = 0.0f; }

    load_chunk(0, 0); CP_COMMIT();
    load_chunk(1, 1); CP_COMMIT();

    const int ar0 = (wid * 16 + qr) * XS_WSTRIDE;
    const int ar1 = ar0 + 8 * XS_WSTRIDE;

#pragma unroll 1
    for (int c = 0; c < NCH; c++) {
        CP_WAIT1();                    // group c complete (c+1 may pend)
        __syncthreads();               // data visible; all warps done with stage (c+2)%3
        if (c + 2 < NCH) load_chunk(c + 2, (c + 2) % NSTAGE);
        CP_COMMIT();                   // uniform group count

        const int s = c % NSTAGE;
        const float* xs = reinterpret_cast<const float*>(dsm + s * STAGE_BYTES);
        const uint32_t whb = sb0 + (uint32_t)s * STAGE_BYTES + WH_OFF;
        const uint32_t wlb = whb + WH_BYTES;

#pragma unroll
        for (int ks = 0; ks < 2; ks++) {
            const int kb = ks * 16 + 2 * qc;
            uint32_t a0h, a0l, a1h, a1l, a2h, a2l, a3h, a3l;
            split_pair(*reinterpret_cast<const float2*>(&xs[ar0 + kb]),     a0h, a0l);
            split_pair(*reinterpret_cast<const float2*>(&xs[ar1 + kb]),     a1h, a1l);
            split_pair(*reinterpret_cast<const float2*>(&xs[ar0 + kb + 8]), a2h, a2l);
            split_pair(*reinterpret_cast<const float2*>(&xs[ar1 + kb + 8]), a3h, a3l);

#pragma unroll
            for (int n = 0; n < 8; n++) {
                // padded rows: row = ks*8 + pair, word off = 8n + qr
                const uint32_t off0 = (uint32_t)((ks * 8 + qc) * B_PSTRIDE
                                                 + (8 * n + qr) * 4);
                const uint32_t off1 = (uint32_t)((ks * 8 + qc + 4) * B_PSTRIDE
                                                 + (8 * n + qr) * 4);
                uint32_t bh0, bh1, bl0, bl1;
                asm volatile("ld.shared.b32 %0, [%1];" : "=r"(bh0) : "r"(whb + off0));
                asm volatile("ld.shared.b32 %0, [%1];" : "=r"(bh1) : "r"(whb + off1));
                asm volatile("ld.shared.b32 %0, [%1];" : "=r"(bl0) : "r"(wlb + off0));
                asm volatile("ld.shared.b32 %0, [%1];" : "=r"(bl1) : "r"(wlb + off1));
                mma_f16(acc[n], a0h, a1h, a2h, a3h, bh0, bh1);
                mma_f16(acc[n], a0h, a1h, a2h, a3h, bl0, bl1);
                mma_f16(acc[n], a0l, a1l, a2l, a3l, bh0, bh1);
            }
        }

        if ((c & 15) == 15) {          // drain: caps fp32 accumulate chain at 96
#pragma unroll
            for (int n = 0; n < 8; n++)
#pragma unroll
                for (int j = 0; j < 4; j++) {
                    sum32[n][j] += acc[n][j];
                    acc[n][j] = 0.0f;
                }
        }
    }
    __syncthreads();

    // ---- epilogue: logits (unscaled) into overlay [128][66] ----
    float* probs = reinterpret_cast<float*>(dsm);
    const float inv_ws = 1.0f / WSCALE;
    {
        const int tr0 = wid * 16 + qr;
#pragma unroll
        for (int n = 0; n < 8; n++) {
            const int cb = n * 8 + qc * 2;
            *reinterpret_cast<float2*>(&probs[tr0 * 66 + cb]) =
                make_float2(sum32[n][0] * inv_ws, sum32[n][1] * inv_ws);
            *reinterpret_cast<float2*>(&probs[(tr0 + 8) * 66 + cb]) =
                make_float2(sum32[n][2] * inv_ws, sum32[n][3] * inv_ws);
        }
    }
    __syncthreads();

    // per-token: softmax + top-2 + gates + outputs
    if (tid < TM) {
        const int t = tid;
        float f[64];
#pragma unroll
        for (int e = 0; e < E_EXP; e++) f[e] = probs[t * 66 + e];
        float mx = f[0];
#pragma unroll
        for (int e = 1; e < E_EXP; e++) mx = fmaxf(mx, f[e]);
        float S = 0.0f, b1 = -1.0f, b2 = -1.0f;
        int i1 = 0, i2 = 0;
#pragma unroll
        for (int e = 0; e < E_EXP; e++) {
            float v = expf(f[e] - mx);
            f[e] = v;
            S += v;
            if (v > b1) { b2 = b1; i2 = i1; b1 = v; i1 = e; }
            else if (v > b2) { b2 = v; i2 = e; }
        }
        const float invS = 1.0f / S;
#pragma unroll
        for (int e = 0; e < E_EXP; e++) probs[t * 66 + e] = f[e] * invS;
        tops[t][0] = i1;
        tops[t][1] = i2;

        const float p1 = b1 * invS, p2 = b2 * invS;
        const float denom = p1 + p2 + 1e-9f;
        const size_t gt = tbase + t;
        out[gt * 2 + 0] = (float)i1;
        out[gt * 2 + 1] = (float)i2;
        out[(size_t)M_TOKENS * 2 + gt * 2 + 0] = p1 / denom;
        out[(size_t)M_TOKENS * 2 + gt * 2 + 1] = p2 / denom;
    }
    __syncthreads();

    // deterministic per-CTA partials
    if (tid < E_EXP) {
        const int e = tid;
        float cnt = 0.0f, sp = 0.0f;
#pragma unroll 4
        for (int t = 0; t < TM; t++) {
            sp  += probs[t * 66 + e];
            cnt += (float)((tops[t][0] == e) + (tops[t][1] == e));
        }
        g_partials[cta * 128 + e]      = cnt;
        g_partials[cta * 128 + 64 + e] = sp;
    }
    __syncthreads();

    // ---- fused aux: last CTA to finish reduces (fixed reduction order) ----
    if (tid == 0) {
        __threadfence();
        s_last = atomicAdd(&g_done, 1u);
    }
    __syncthreads();
    if (s_last == NCTA - 1) {
        __threadfence();
        float* sC = probs;            // reuse overlay
        float* sP = probs + 64;
        float* red = probs + 128;
        if (tid < 128) {
            const int e = tid & 63, h = tid >> 6;
            float sv = 0.0f;
#pragma unroll 4
            for (int b = 0; b < NCTA; b++)
                sv += __ldcg(&g_partials[b * 128 + h * 64 + e]);
            if (h == 0) sC[e] = sv; else sP[e] = sv;
        }
        __syncthreads();
        if (tid < 64) red[tid] = sC[tid] * sP[tid];
        __syncthreads();
#pragma unroll
        for (int s = 32; s > 0; s >>= 1) {
            if (tid < s) red[tid] += red[tid + s];
            __syncthreads();
        }
        if (tid == 0) {
            out[(size_t)M_TOKENS * 4] =
                0.01f * 64.0f * red[0] / (32768.0f * 16384.0f);
            g_done = 0;               // reset for next graph replay
        }
    }
}

extern "C" void kernel_launch(void* const* d_in, const int* in_sizes, int n_in,
                              void* d_out, int out_size)
{
    const float* x = (const float*)d_in[0];   // [4,4096,2048] f32
    const float* W = (const float*)d_in[1];   // [64,2048] f32
    float* out = (float*)d_out;               // [32768 idx | 32768 gates | 1 aux]

    cudaFuncSetAttribute(router_f16,
                         cudaFuncAttributeMaxDynamicSharedMemorySize, DYN_BYTES);

    wsplit_kernel<<<64, 256>>>(W);
    router_f16<<<NCTA, NTHREADS, DYN_BYTES>>>(x, out);
}